// round 9
// baseline (speedup 1.0000x reference)
#include <cuda_runtime.h>
#include <cuda_bf16.h>
#include <math.h>

typedef unsigned int u32;
typedef unsigned long long u64;

#define NN 10000
#define NE 50000
#define IN_CH 32
#define EIN 16
#define GIN 8
#define HID 64
#define NG 64
#define EPS_BN 1e-5f

#define NODE_G 68     // nodes per fused CTA -> 148 CTAs = one wave
#define MPAD 96       // mma M pad (6 x 16)
#define ECAP 384      // SMEM edge accumulator capacity
#define ASTRIDE 200   // bf16 elems per A/B SMEM row (400B)
#define QSTRIDE 72    // f32 elems per Qs row

// ---------------- device scratch ----------------
__device__ __align__(16) __nv_bfloat16 g_Wbf[8192 * 192]; // [j=c*64+o][3K pack hi|lo|hi], stride 192
__device__ float g_Ht [(size_t)128 * NE];  // H transposed, perm-ordered: [c][p]
__device__ float g_xA[NN * HID];
__device__ float g_xB[NN * HID];
__device__ float g_agg[NN * HID];
__device__ float g_xb [NN * HID];
__device__ int   g_cnt[NN];
__device__ int   g_off[NN + 1];
__device__ int   g_cur[NN];
__device__ int   g_perm[NE];
__device__ int   g_psrc[NE];
__device__ int   g_pdst[NE];
__device__ float g_bnsum[HID];
__device__ float g_bnsq [HID];
__device__ float g_pool[NG * HID];

// ---------------- PTX helpers (sm_80+ baseline) ----------------
__device__ __forceinline__ u32 smem_u32(const void* p) {
    u32 a;
    asm("{ .reg .u64 t; cvta.to.shared.u64 t, %1; cvt.u32.u64 %0, t; }" : "=r"(a) : "l"(p));
    return a;
}
__device__ __forceinline__ void ldsm_x4(u32& r0, u32& r1, u32& r2, u32& r3, u32 addr) {
    asm volatile("ldmatrix.sync.aligned.m8n8.x4.shared.b16 {%0,%1,%2,%3}, [%4];"
                 : "=r"(r0), "=r"(r1), "=r"(r2), "=r"(r3) : "r"(addr));
}
__device__ __forceinline__ void mma16816(float* c, const u32* a, const u32* b) {
    asm volatile(
        "mma.sync.aligned.m16n8k16.row.col.f32.bf16.bf16.f32 "
        "{%0,%1,%2,%3}, {%4,%5,%6,%7}, {%8,%9}, {%0,%1,%2,%3};"
        : "+f"(c[0]), "+f"(c[1]), "+f"(c[2]), "+f"(c[3])
        : "r"(a[0]), "r"(a[1]), "r"(a[2]), "r"(a[3]), "r"(b[0]), "r"(b[1]));
}
__device__ __forceinline__ void cpasync16(u32 saddr, const void* gaddr) {
    asm volatile("cp.async.ca.shared.global [%0], [%1], 16;" :: "r"(saddr), "l"(gaddr) : "memory");
}
__device__ __forceinline__ void cp_commit() {
    asm volatile("cp.async.commit_group;" ::: "memory");
}
__device__ __forceinline__ void cp_wait0() {
    asm volatile("cp.async.wait_group 0;" ::: "memory");
}
__device__ __forceinline__ void cp_wait1() {
    asm volatile("cp.async.wait_group 1;" ::: "memory");
}
__device__ __forceinline__ void bar_sync(int id, int cnt) {
    asm volatile("bar.sync %0, %1;" :: "r"(id), "r"(cnt) : "memory");
}
__device__ __forceinline__ void bar_arrive(int id, int cnt) {
    asm volatile("bar.arrive %0, %1;" :: "r"(id), "r"(cnt) : "memory");
}
__device__ __forceinline__ void membar_cta() {
    asm volatile("membar.cta;" ::: "memory");
}

// ---------------- CSR build ----------------
__global__ void k_zero_cnt() {
    int i = blockIdx.x * blockDim.x + threadIdx.x;
    if (i < NN) g_cnt[i] = 0;
}
__global__ void k_count(const int* __restrict__ src) {
    int e = blockIdx.x * blockDim.x + threadIdx.x;
    if (e < NE) atomicAdd(&g_cnt[src[e]], 1);
}
__global__ void k_scan() {
    __shared__ int part[1024];
    int t = threadIdx.x;
    const int CH = (NN + 1023) / 1024;
    int base = t * CH;
    int s = 0;
    for (int i = 0; i < CH; i++) {
        int idx = base + i;
        if (idx < NN) s += g_cnt[idx];
    }
    part[t] = s;
    __syncthreads();
    for (int d = 1; d < 1024; d <<= 1) {
        int v = (t >= d) ? part[t - d] : 0;
        __syncthreads();
        part[t] += v;
        __syncthreads();
    }
    int pre = (t == 0) ? 0 : part[t - 1];
    for (int i = 0; i < CH; i++) {
        int idx = base + i;
        if (idx < NN) {
            g_off[idx] = pre;
            g_cur[idx] = pre;
            pre += g_cnt[idx];
        }
    }
    if (t == 1023) g_off[NN] = part[1023];
}
__global__ void k_scatter(const int* __restrict__ src, const int* __restrict__ dst) {
    int e = blockIdx.x * blockDim.x + threadIdx.x;
    if (e < NE) {
        int s = src[e];
        int p = atomicAdd(&g_cur[s], 1);
        g_perm[p] = e;
        g_psrc[p] = s;
        g_pdst[p] = dst[e];
    }
}

// ---------------- W2 split, coalesced via SMEM transpose ----------------
__global__ void k_wsplit2(const float* __restrict__ w2, int K) {
    __shared__ float ws[64 * 65];
    int c = blockIdx.x;
    int t = threadIdx.x;  // 256
    for (int idx = t; idx < K * 64; idx += 256) {
        int k = idx >> 6, o = idx & 63;
        ws[k * 65 + o] = w2[(size_t)c * (K * 64) + idx];
    }
    __syncthreads();
    int wid = t >> 5, lane = t & 31;
    int np = (3 * K) >> 1;
    u32* Wr = (u32*)g_Wbf;
    for (int o = wid; o < 64; o += 8) {
        size_t j = (size_t)(c * 64 + o);
        for (int pc = lane; pc < np; pc += 32) {
            int j2 = pc * 2;
            int b = j2 / K, kk = j2 - b * K;
            float v0 = ws[kk * 65 + o];
            float v1 = ws[(kk + 1) * 65 + o];
            __nv_bfloat16 h0 = __float2bfloat16(v0);
            __nv_bfloat16 h1 = __float2bfloat16(v1);
            u32 pk;
            if (b == 1) {
                __nv_bfloat16 l0 = __float2bfloat16(v0 - __bfloat162float(h0));
                __nv_bfloat16 l1 = __float2bfloat16(v1 - __bfloat162float(h1));
                pk = (u32)__bfloat16_as_ushort(l0) | ((u32)__bfloat16_as_ushort(l1) << 16);
            } else {
                pk = (u32)__bfloat16_as_ushort(h0) | ((u32)__bfloat16_as_ushort(h1) << 16);
            }
            Wr[j * 96 + pc] = pk;
        }
    }
}

// ---------------- edge hidden, transposed + perm-ordered: g_Ht[c][p] ----------------
#define EPB 32
__global__ void k_edge_h(const float* __restrict__ ea,
                         const float* __restrict__ w1,
                         const float* __restrict__ b1) {
    __shared__ float ws[EIN * 128];
    __shared__ float eas[EPB][17];
    __shared__ int   es[EPB];
    __shared__ float Hs[128][EPB + 1];
    int t = threadIdx.x;   // 128
    int p0 = blockIdx.x * EPB;
    int pe = min(EPB, NE - p0);
    for (int idx = t; idx < EIN * 128; idx += 128) ws[idx] = w1[idx];
    if (t < pe) es[t] = g_perm[p0 + t];
    __syncthreads();
    for (int idx = t; idx < pe * EIN; idx += 128) {
        int ei = idx >> 4, i = idx & 15;
        eas[ei][i] = ea[(size_t)es[ei] * EIN + i];
    }
    __syncthreads();
    int c = t;
    float b = b1[c];
    for (int ei = 0; ei < pe; ei++) {
        float s = b;
#pragma unroll
        for (int i = 0; i < EIN; i++) s += eas[ei][i] * ws[i * 128 + c];
        Hs[c][ei] = fmaxf(s, 0.f);
    }
    __syncthreads();
    for (int idx = t; idx < 128 * EPB; idx += 128) {
        int cc = idx >> 5, ei = idx & 31;
        if (ei < pe) g_Ht[(size_t)cc * NE + p0 + ei] = Hs[cc][ei];
    }
}

// ---------------- node pre: agg = x@root + bias ; xb = x@b2resh ----------------
__global__ void k_node_pre(const float* __restrict__ x, int C,
                           const float* __restrict__ root,
                           const float* __restrict__ bias,
                           const float* __restrict__ b2) {
    __shared__ float xs[4][64];
    __shared__ float rs[64 * 64];
    __shared__ float b2s[64 * 64];
    int t = threadIdx.x;
    int o = t & 63, s = t >> 6;
    for (int i = t; i < C * 64; i += 256) { rs[i] = root[i]; b2s[i] = b2[i]; }
    int n = blockIdx.x * 4 + s;
    if (n < NN) {
        for (int k = o; k < C; k += 64) xs[s][k] = x[(size_t)n * C + k];
    }
    __syncthreads();
    if (n < NN) {
        float a = bias[o], xbv = 0.f;
        for (int k = 0; k < C; k++) {
            float xv = xs[s][k];
            a   += xv * rs [k * 64 + o];
            xbv += xv * b2s[k * 64 + o];
        }
        g_agg[n * 64 + o] = a;
        g_xb [n * 64 + o] = xbv;
    }
}

// ---------------- FUSED v3: warp-specialized producers (mma) + consumers (edges) ----------------
// SMEM: As 96x200 bf16 @0 (38400) | Bs 2x 64x200 bf16 @38400 (51200) |
//       Qs 2x 68x72 f32 @89600 (39168) | macc 384x64 f32 @128768 (98304) | sl @227072 (1536)
#define FB_BS 38400
#define FB_QS 89600
#define FB_MA 128768
#define FB_SL 227072
#define FB_TOTAL 228608
// barriers: FULL0=1 FULL1=2 EMPTY0=3 EMPTY1=4 | producer-internal=5 | consumer-internal=6

template<int K>
__global__ void __launch_bounds__(512, 1) k_fused(const float* __restrict__ X) {
    constexpr int NK16 = (3 * K) / 16;   // 6 or 12
    constexpr int HALF = K / 2;
    extern __shared__ char smem[];
    __nv_bfloat16* As = (__nv_bfloat16*)smem;
    float* Qs   = (float*)(smem + FB_QS);
    float* macc = (float*)(smem + FB_MA);
    int*   sl   = (int*)(smem + FB_SL);

    int t = threadIdx.x, w = t >> 5, lane = t & 31;
    int n0 = blockIdx.x * NODE_G;
    int nend = min(n0 + NODE_G, NN);
    int p0 = g_off[n0];
    int p1 = g_off[nend];
    int ce = p1 - p0;
    if (ce <= 0) return;              // uniform across CTA
    int ceM = min(ce, ECAP);
    int npair = (ceM + 1) >> 1;

    u32 a_base = smem_u32(As);
    u32 b_base = smem_u32(smem + FB_BS);

    if (w < 12) {
        // ========== producers: 12 warps, 384 threads ==========
        const char* Wsrc = (const char*)g_Wbf;
        // prefetch B(0), B(1)
        for (int i = t; i < 64 * 24; i += 384) {
            int r = i / 24, q = i - r * 24;
            cpasync16(b_base + (u32)(r * 400 + q * 16), Wsrc + r * 384 + q * 16);
        }
        cp_commit();
        for (int i = t; i < 64 * 24; i += 384) {
            int r = i / 24, q = i - r * 24;
            cpasync16(b_base + (u32)(25600 + r * 400 + q * 16), Wsrc + (size_t)(64 + r) * 384 + q * 16);
        }
        cp_commit();
        // A' fill: [hi | hi | lo]
        for (int idx = t; idx < MPAD * HALF; idx += 384) {
            int r = idx / HALF, kp = idx - r * HALF;
            int k = kp * 2;
            int n = n0 + r;
            float v0 = 0.f, v1 = 0.f;
            if (r < NODE_G && n < NN) {
                v0 = X[(size_t)n * K + k];
                v1 = X[(size_t)n * K + k + 1];
            }
            __nv_bfloat16 h0 = __float2bfloat16(v0);
            __nv_bfloat16 h1 = __float2bfloat16(v1);
            __nv_bfloat16 l0 = __float2bfloat16(v0 - __bfloat162float(h0));
            __nv_bfloat16 l1 = __float2bfloat16(v1 - __bfloat162float(h1));
            u32 hp = (u32)__bfloat16_as_ushort(h0) | ((u32)__bfloat16_as_ushort(h1) << 16);
            u32 lp = (u32)__bfloat16_as_ushort(l0) | ((u32)__bfloat16_as_ushort(l1) << 16);
            u32* Arow = (u32*)As + r * 100;
            Arow[kp]            = hp;
            Arow[HALF + kp]     = hp;
            Arow[2 * HALF + kp] = lp;
        }
        int wm = (w % 6) * 16;
        int wn = (w / 6) * 32;
        for (int it = 0; it < 128; it++) {
            int b = it & 1;
            if (it >= 2) bar_sync(3 + b, 512);       // wait Qs[b] consumed (it-2)
            if (it == 127) cp_wait0(); else cp_wait1();
            bar_sync(5, 384);                        // B(it) + A visible to all producers
            u32 bb = b_base + (u32)(b * 25600);
            float acc[4][4];
#pragma unroll
            for (int jb = 0; jb < 4; jb++)
#pragma unroll
                for (int q = 0; q < 4; q++) acc[jb][q] = 0.f;
#pragma unroll
            for (int ks = 0; ks < NK16; ks++) {
                int k0 = ks * 16;
                u32 a[4];
                ldsm_x4(a[0], a[1], a[2], a[3],
                        a_base + (u32)(((wm + (lane & 15)) * ASTRIDE + k0 + (lane >> 4) * 8) * 2));
                u32 bf[2][4];
#pragma unroll
                for (int g = 0; g < 2; g++) {
                    int row = wn + g * 16 + ((lane >> 4) << 3) + (lane & 7);
                    int col = k0 + ((lane >> 3) & 1) * 8;
                    ldsm_x4(bf[g][0], bf[g][1], bf[g][2], bf[g][3],
                            bb + (u32)((row * ASTRIDE + col) * 2));
                }
                mma16816(acc[0], a, &bf[0][0]);
                mma16816(acc[1], a, &bf[0][2]);
                mma16816(acc[2], a, &bf[1][0]);
                mma16816(acc[3], a, &bf[1][2]);
            }
            bar_sync(5, 384);                        // all producers done reading Bs[b]
            if (it < 126) {
                const char* Wn = (const char*)g_Wbf + (size_t)(it + 2) * 64 * 384;
                for (int i = t; i < 64 * 24; i += 384) {
                    int r = i / 24, q = i - r * 24;
                    cpasync16(b_base + (u32)(b * 25600 + r * 400 + q * 16), Wn + r * 384 + q * 16);
                }
            }
            cp_commit();
            float* Qb = Qs + b * (NODE_G * QSTRIDE);
            int m0 = wm + (lane >> 2);
#pragma unroll
            for (int jb = 0; jb < 4; jb++) {
                int col = wn + jb * 8 + (lane & 3) * 2;
                if (m0 < NODE_G)
                    *(float2*)&Qb[m0 * QSTRIDE + col] = make_float2(acc[jb][0], acc[jb][1]);
                if (m0 + 8 < NODE_G)
                    *(float2*)&Qb[(m0 + 8) * QSTRIDE + col] = make_float2(acc[jb][2], acc[jb][3]);
            }
            membar_cta();
            bar_arrive(1 + b, 512);                  // Qs[b] full
        }
    } else {
        // ========== consumers: 4 warps, 128 threads ==========
        int et = t - 384;
        int ew = w - 12;
        for (int i = et; i < ceM; i += 128) sl[i] = g_psrc[p0 + i] - n0;
        {
            float4* m4 = (float4*)macc;
            for (int i = et; i < ECAP * 16; i += 128) m4[i] = make_float4(0.f, 0.f, 0.f, 0.f);
        }
        bar_sync(6, 128);
        int eh = lane >> 4, ol = lane & 15;
        float* Q0 = Qs;
        float* Q1 = Qs + NODE_G * QSTRIDE;
        for (int itp = 0; itp < 64; itp++) {
            bar_sync(1, 512);                        // Qs[0] full (c = 2*itp)
            bar_sync(2, 512);                        // Qs[1] full (c = 2*itp+1)
            const float* H0 = g_Ht + (size_t)(2 * itp) * NE + p0;
            const float* H1 = H0 + NE;
            for (int pr = ew; pr < npair; pr += 4) {
                int e = 2 * pr + eh;
                if (e < ceM) {
                    float h0 = H0[e], h1 = H1[e];
                    int s = sl[e];
                    float4 q0 = *(const float4*)&Q0[s * QSTRIDE + 4 * ol];
                    float4 q1 = *(const float4*)&Q1[s * QSTRIDE + 4 * ol];
                    float4 m = *(float4*)&macc[e * 64 + 4 * ol];
                    m.x += h0 * q0.x + h1 * q1.x;
                    m.y += h0 * q0.y + h1 * q1.y;
                    m.z += h0 * q0.z + h1 * q1.z;
                    m.w += h0 * q0.w + h1 * q1.w;
                    *(float4*)&macc[e * 64 + 4 * ol] = m;
                }
            }
            for (int e = ceM + (et >> 6); e < ce; e += 2) {   // rare overflow edges
                int o = et & 63;
                float h0 = H0[e], h1 = H1[e];
                int s = g_psrc[p0 + e] - n0;
                float v = h0 * Q0[s * QSTRIDE + o] + h1 * Q1[s * QSTRIDE + o];
                atomicAdd(&g_agg[(size_t)g_pdst[p0 + e] * 64 + o], v);
            }
            if (itp < 63) {
                bar_arrive(3, 512);                  // Qs[0] empty
                bar_arrive(4, 512);                  // Qs[1] empty
            }
        }
        // flush macc + xb
        for (int pr = ew; pr < npair; pr += 4) {
            int e = 2 * pr + eh;
            if (e < ceM) {
                int p = p0 + e;
                int d = g_pdst[p];
                int sg = n0 + sl[e];
                float4 m = *(float4*)&macc[e * 64 + 4 * ol];
                float4 xv = *(const float4*)&g_xb[(size_t)sg * 64 + 4 * ol];
                atomicAdd(&g_agg[(size_t)d * 64 + 4 * ol],     m.x + xv.x);
                atomicAdd(&g_agg[(size_t)d * 64 + 4 * ol + 1], m.y + xv.y);
                atomicAdd(&g_agg[(size_t)d * 64 + 4 * ol + 2], m.z + xv.z);
                atomicAdd(&g_agg[(size_t)d * 64 + 4 * ol + 3], m.w + xv.w);
            }
        }
        for (int e = ceM + (et >> 6); e < ce; e += 2) {
            int p = p0 + e, o = et & 63;
            atomicAdd(&g_agg[(size_t)g_pdst[p] * 64 + o], g_xb[(size_t)g_psrc[p] * 64 + o]);
        }
    }
}

// ---------------- batch norm ----------------
__global__ void k_bn_zero() {
    int t = threadIdx.x;
    if (t < HID) { g_bnsum[t] = 0.f; g_bnsq[t] = 0.f; }
}
__global__ void k_bn_stats() {
    int t = threadIdx.x;
    int o = t & 63, s = t >> 6;
    float sum = 0.f, sq = 0.f;
    for (int n = blockIdx.x * 4 + s; n < NN; n += gridDim.x * 4) {
        float v = g_agg[(size_t)n * 64 + o];
        sum += v; sq += v * v;
    }
    __shared__ float ssum[256], ssq[256];
    ssum[t] = sum; ssq[t] = sq;
    __syncthreads();
    if (t < 128) { ssum[t] += ssum[t + 128]; ssq[t] += ssq[t + 128]; }
    __syncthreads();
    if (t < 64) {
        atomicAdd(&g_bnsum[t], ssum[t] + ssum[t + 64]);
        atomicAdd(&g_bnsq [t], ssq [t] + ssq [t + 64]);
    }
}
__global__ void k_bn_apply(const float* __restrict__ gamma,
                           const float* __restrict__ beta,
                           float* __restrict__ xout) {
    int i = blockIdx.x * blockDim.x + threadIdx.x;
    if (i >= NN * 64) return;
    int o = i & 63;
    float mu  = g_bnsum[o] * (1.f / NN);
    float var = g_bnsq[o] * (1.f / NN) - mu * mu;
    float v = gamma[o] * (g_agg[i] - mu) * rsqrtf(var + EPS_BN) + beta[o];
    xout[i] = fmaxf(v, 0.f);
}

// ---------------- pooling + final MLP ----------------
__global__ void k_pool_init() {
    int i = blockIdx.x * blockDim.x + threadIdx.x;
    if (i < NG * HID) g_pool[i] = 0.f;
}
__global__ void k_pool(const float* __restrict__ xl, const int* __restrict__ batch) {
    int i = blockIdx.x * blockDim.x + threadIdx.x;
    if (i >= NN * 64) return;
    int n = i >> 6, o = i & 63;
    int g = batch[n];
    atomicMax(reinterpret_cast<unsigned int*>(&g_pool[g * 64 + o]), __float_as_uint(xl[i]));
}
__global__ void k_final(const float* __restrict__ u,
                        const float* __restrict__ w1, const float* __restrict__ b1,
                        const float* __restrict__ w2, const float* __restrict__ b2,
                        float* __restrict__ out) {
    int g = blockIdx.x;
    int j = threadIdx.x;
    __shared__ float cat[72];
    __shared__ float red[64];
    if (j < 64) cat[j] = g_pool[g * 64 + j];
    if (j < 8)  cat[64 + j] = u[g * 8 + j];
    __syncthreads();
    float h = b1[j];
#pragma unroll
    for (int k = 0; k < 72; k++) h += cat[k] * w1[k * 64 + j];
    h = fmaxf(h, 0.f);
    red[j] = h * w2[j];
    __syncthreads();
    for (int s = 32; s > 0; s >>= 1) {
        if (j < s) red[j] += red[j + s];
        __syncthreads();
    }
    if (j == 0) out[g] = red[0] + b2[0];
}

// ---------------- host ----------------
extern "C" void kernel_launch(void* const* d_in, const int* in_sizes, int n_in,
                              void* d_out, int out_size) {
    const float* x       = (const float*)d_in[0];
    const int*   ei      = (const int*)  d_in[1];
    const float* ea      = (const float*)d_in[2];
    const int*   batch   = (const int*)  d_in[3];
    const float* u       = (const float*)d_in[4];
    const float* enn0_w1 = (const float*)d_in[5];
    const float* enn0_b1 = (const float*)d_in[6];
    const float* enn0_w2 = (const float*)d_in[7];
    const float* enn0_b2 = (const float*)d_in[8];
    const float* root0   = (const float*)d_in[9];
    const float* bias0   = (const float*)d_in[10];
    const float* gamma0  = (const float*)d_in[11];
    const float* beta0   = (const float*)d_in[12];
    const float* enn_w1  = (const float*)d_in[13];
    const float* enn_b1  = (const float*)d_in[14];
    const float* enn_w2  = (const float*)d_in[15];
    const float* enn_b2  = (const float*)d_in[16];
    const float* root_l  = (const float*)d_in[17];
    const float* bias_l  = (const float*)d_in[18];
    const float* gamma_l = (const float*)d_in[19];
    const float* beta_l  = (const float*)d_in[20];
    const float* pp_w1   = (const float*)d_in[21];
    const float* pp_b1   = (const float*)d_in[22];
    const float* pp_w2   = (const float*)d_in[23];
    const float* pp_b2   = (const float*)d_in[24];

    const int* src  = ei;
    const int* dste = ei + NE;

    cudaFuncSetAttribute(k_fused<IN_CH>, cudaFuncAttributeMaxDynamicSharedMemorySize, FB_TOTAL);
    cudaFuncSetAttribute(k_fused<HID>,  cudaFuncAttributeMaxDynamicSharedMemorySize, FB_TOTAL);

    void* pA; cudaGetSymbolAddress(&pA, g_xA);
    void* pB; cudaGetSymbolAddress(&pB, g_xB);
    float* xA = (float*)pA;
    float* xB = (float*)pB;

    k_zero_cnt<<<(NN + 255) / 256, 256>>>();
    k_count  <<<(NE + 255) / 256, 256>>>(src);
    k_scan   <<<1, 1024>>>();
    k_scatter<<<(NE + 255) / 256, 256>>>(src, dste);

    const float* xin = x;
    float* xout = xA;

    for (int l = 0; l < 4; l++) {
        const float *w1, *b1, *w2, *b2, *rt, *bs, *gm, *bt;
        int C = (l == 0) ? IN_CH : HID;
        if (l == 0) {
            w1 = enn0_w1; b1 = enn0_b1; w2 = enn0_w2; b2 = enn0_b2;
            rt = root0; bs = bias0; gm = gamma0; bt = beta0;
        } else {
            int m = l - 1;
            w1 = enn_w1 + (size_t)m * EIN * 128;
            b1 = enn_b1 + (size_t)m * 128;
            w2 = enn_w2 + (size_t)m * 128 * 4096;
            b2 = enn_b2 + (size_t)m * 4096;
            rt = root_l + (size_t)m * 64 * 64;
            bs = bias_l + (size_t)m * 64;
            gm = gamma_l + (size_t)m * 64;
            bt = beta_l + (size_t)m * 64;
        }
        k_wsplit2 <<<128, 256>>>(w2, C);
        k_edge_h  <<<(NE + EPB - 1) / EPB, 128>>>(ea, w1, b1);
        k_node_pre<<<(NN + 3) / 4, 256>>>(xin, C, rt, bs, b2);
        if (l == 0) k_fused<IN_CH><<<148, 512, FB_TOTAL>>>(xin);
        else        k_fused<HID> <<<148, 512, FB_TOTAL>>>(xin);
        k_bn_zero <<<1, 64>>>();
        k_bn_stats<<<128, 256>>>();
        k_bn_apply<<<(NN * 64 + 255) / 256, 256>>>(gm, bt, xout);

        xin = xout;
        xout = (xout == xA) ? xB : xA;
    }

    k_pool_init<<<(NG * HID + 255) / 256, 256>>>();
    k_pool     <<<(NN * 64 + 255) / 256, 256>>>(xin, batch);
    k_final    <<<NG, 64>>>(u, pp_w1, pp_b1, pp_w2, pp_b2, (float*)d_out);
}

// round 10
// speedup vs baseline: 2.8503x; 2.8503x over previous
#include <cuda_runtime.h>
#include <cuda_bf16.h>
#include <math.h>

typedef unsigned int u32;
typedef unsigned long long u64;

#define NN 10000
#define NE 50000
#define IN_CH 32
#define EIN 16
#define GIN 8
#define HID 64
#define NG 64
#define EPS_BN 1e-5f

#define NODE_G 68     // nodes per fused CTA -> 148 CTAs = one wave
#define MPAD 96       // mma M pad (6 x 16)
#define ECAP 384      // register-edge capacity per CTA (16 warps x 24)
#define EWMAX 24      // max edges owned per warp
#define ASTRIDE 200   // bf16 elems per A/B SMEM row (400B)
#define QSTRIDE 136   // f32 elems per Qs row

// ---------------- device scratch ----------------
__device__ __align__(16) __nv_bfloat16 g_Wbf[8192 * 192]; // [j=c*64+o][3K pack hi|lo|hi], stride 192
__device__ float g_Ht [(size_t)128 * NE];  // H transposed, perm-ordered: [c][p]
__device__ float g_xA[NN * HID];
__device__ float g_xB[NN * HID];
__device__ float g_agg[NN * HID];
__device__ float g_xb [NN * HID];
__device__ int   g_cnt[NN];
__device__ int   g_off[NN + 1];
__device__ int   g_cur[NN];
__device__ int   g_perm[NE];
__device__ int   g_psrc[NE];
__device__ int   g_pdst[NE];
__device__ float g_bnsum[HID];
__device__ float g_bnsq [HID];
__device__ float g_pool[NG * HID];

// ---------------- PTX helpers (sm_80+ baseline) ----------------
__device__ __forceinline__ u32 smem_u32(const void* p) {
    u32 a;
    asm("{ .reg .u64 t; cvta.to.shared.u64 t, %1; cvt.u32.u64 %0, t; }" : "=r"(a) : "l"(p));
    return a;
}
__device__ __forceinline__ void ldsm_x4(u32& r0, u32& r1, u32& r2, u32& r3, u32 addr) {
    asm volatile("ldmatrix.sync.aligned.m8n8.x4.shared.b16 {%0,%1,%2,%3}, [%4];"
                 : "=r"(r0), "=r"(r1), "=r"(r2), "=r"(r3) : "r"(addr));
}
__device__ __forceinline__ void ldsm_x2(u32& r0, u32& r1, u32 addr) {
    asm volatile("ldmatrix.sync.aligned.m8n8.x2.shared.b16 {%0,%1}, [%2];"
                 : "=r"(r0), "=r"(r1) : "r"(addr));
}
__device__ __forceinline__ void mma16816(float* c, const u32* a, const u32* b) {
    asm volatile(
        "mma.sync.aligned.m16n8k16.row.col.f32.bf16.bf16.f32 "
        "{%0,%1,%2,%3}, {%4,%5,%6,%7}, {%8,%9}, {%0,%1,%2,%3};"
        : "+f"(c[0]), "+f"(c[1]), "+f"(c[2]), "+f"(c[3])
        : "r"(a[0]), "r"(a[1]), "r"(a[2]), "r"(a[3]), "r"(b[0]), "r"(b[1]));
}
__device__ __forceinline__ void cpasync16(u32 saddr, const void* gaddr) {
    asm volatile("cp.async.ca.shared.global [%0], [%1], 16;" :: "r"(saddr), "l"(gaddr) : "memory");
}
__device__ __forceinline__ void cpasync4(u32 saddr, const void* gaddr) {
    asm volatile("cp.async.ca.shared.global [%0], [%1], 4;" :: "r"(saddr), "l"(gaddr) : "memory");
}
__device__ __forceinline__ void cp_commit() {
    asm volatile("cp.async.commit_group;" ::: "memory");
}
__device__ __forceinline__ void cp_wait0() {
    asm volatile("cp.async.wait_group 0;" ::: "memory");
}

// ---------------- CSR build ----------------
__global__ void k_zero_cnt() {
    int i = blockIdx.x * blockDim.x + threadIdx.x;
    if (i < NN) g_cnt[i] = 0;
}
__global__ void k_count(const int* __restrict__ src) {
    int e = blockIdx.x * blockDim.x + threadIdx.x;
    if (e < NE) atomicAdd(&g_cnt[src[e]], 1);
}
__global__ void k_scan() {
    __shared__ int part[1024];
    int t = threadIdx.x;
    const int CH = (NN + 1023) / 1024;
    int base = t * CH;
    int s = 0;
    for (int i = 0; i < CH; i++) {
        int idx = base + i;
        if (idx < NN) s += g_cnt[idx];
    }
    part[t] = s;
    __syncthreads();
    for (int d = 1; d < 1024; d <<= 1) {
        int v = (t >= d) ? part[t - d] : 0;
        __syncthreads();
        part[t] += v;
        __syncthreads();
    }
    int pre = (t == 0) ? 0 : part[t - 1];
    for (int i = 0; i < CH; i++) {
        int idx = base + i;
        if (idx < NN) {
            g_off[idx] = pre;
            g_cur[idx] = pre;
            pre += g_cnt[idx];
        }
    }
    if (t == 1023) g_off[NN] = part[1023];
}
__global__ void k_scatter(const int* __restrict__ src, const int* __restrict__ dst) {
    int e = blockIdx.x * blockDim.x + threadIdx.x;
    if (e < NE) {
        int s = src[e];
        int p = atomicAdd(&g_cur[s], 1);
        g_perm[p] = e;
        g_psrc[p] = s;
        g_pdst[p] = dst[e];
    }
}

// ---------------- W2 split, coalesced via SMEM transpose ----------------
__global__ void k_wsplit2(const float* __restrict__ w2, int K) {
    __shared__ float ws[64 * 65];
    int c = blockIdx.x;
    int t = threadIdx.x;  // 256
    for (int idx = t; idx < K * 64; idx += 256) {
        int k = idx >> 6, o = idx & 63;
        ws[k * 65 + o] = w2[(size_t)c * (K * 64) + idx];
    }
    __syncthreads();
    int wid = t >> 5, lane = t & 31;
    int np = (3 * K) >> 1;
    u32* Wr = (u32*)g_Wbf;
    for (int o = wid; o < 64; o += 8) {
        size_t j = (size_t)(c * 64 + o);
        for (int pc = lane; pc < np; pc += 32) {
            int j2 = pc * 2;
            int b = j2 / K, kk = j2 - b * K;
            float v0 = ws[kk * 65 + o];
            float v1 = ws[(kk + 1) * 65 + o];
            __nv_bfloat16 h0 = __float2bfloat16(v0);
            __nv_bfloat16 h1 = __float2bfloat16(v1);
            u32 pk;
            if (b == 1) {
                __nv_bfloat16 l0 = __float2bfloat16(v0 - __bfloat162float(h0));
                __nv_bfloat16 l1 = __float2bfloat16(v1 - __bfloat162float(h1));
                pk = (u32)__bfloat16_as_ushort(l0) | ((u32)__bfloat16_as_ushort(l1) << 16);
            } else {
                pk = (u32)__bfloat16_as_ushort(h0) | ((u32)__bfloat16_as_ushort(h1) << 16);
            }
            Wr[j * 96 + pc] = pk;
        }
    }
}

// ---------------- edge hidden, transposed + perm-ordered: g_Ht[c][p] ----------------
#define EPB 32
__global__ void k_edge_h(const float* __restrict__ ea,
                         const float* __restrict__ w1,
                         const float* __restrict__ b1) {
    __shared__ float ws[EIN * 128];
    __shared__ float eas[EPB][17];
    __shared__ int   es[EPB];
    __shared__ float Hs[128][EPB + 1];
    int t = threadIdx.x;   // 128
    int p0 = blockIdx.x * EPB;
    int pe = min(EPB, NE - p0);
    for (int idx = t; idx < EIN * 128; idx += 128) ws[idx] = w1[idx];
    if (t < pe) es[t] = g_perm[p0 + t];
    __syncthreads();
    for (int idx = t; idx < pe * EIN; idx += 128) {
        int ei = idx >> 4, i = idx & 15;
        eas[ei][i] = ea[(size_t)es[ei] * EIN + i];
    }
    __syncthreads();
    int c = t;
    float b = b1[c];
    for (int ei = 0; ei < pe; ei++) {
        float s = b;
#pragma unroll
        for (int i = 0; i < EIN; i++) s += eas[ei][i] * ws[i * 128 + c];
        Hs[c][ei] = fmaxf(s, 0.f);
    }
    __syncthreads();
    for (int idx = t; idx < 128 * EPB; idx += 128) {
        int cc = idx >> 5, ei = idx & 31;
        if (ei < pe) g_Ht[(size_t)cc * NE + p0 + ei] = Hs[cc][ei];
    }
}

// ---------------- node pre: agg = x@root + bias ; xb = x@b2resh ----------------
__global__ void k_node_pre(const float* __restrict__ x, int C,
                           const float* __restrict__ root,
                           const float* __restrict__ bias,
                           const float* __restrict__ b2) {
    __shared__ float xs[4][64];
    __shared__ float rs[64 * 64];
    __shared__ float b2s[64 * 64];
    int t = threadIdx.x;
    int o = t & 63, s = t >> 6;
    for (int i = t; i < C * 64; i += 256) { rs[i] = root[i]; b2s[i] = b2[i]; }
    int n = blockIdx.x * 4 + s;
    if (n < NN) {
        for (int k = o; k < C; k += 64) xs[s][k] = x[(size_t)n * C + k];
    }
    __syncthreads();
    if (n < NN) {
        float a = bias[o], xbv = 0.f;
        for (int k = 0; k < C; k++) {
            float xv = xs[s][k];
            a   += xv * rs [k * 64 + o];
            xbv += xv * b2s[k * 64 + o];
        }
        g_agg[n * 64 + o] = a;
        g_xb [n * 64 + o] = xbv;
    }
}

// ---------------- FUSED v4: mma + register-resident edge accumulation ----------------
// SMEM (bytes): As 96x200 bf16 @0 (38400) | Bs 128x200 bf16 @38400 (51200) |
//               Qs 68x136 f32 @89600 (36992) | hs 2x2x384 f32 @126592 (12288) | sl @138880 (1536)
#define FB_BS 38400
#define FB_QS 89600
#define FB_HS 126592
#define FB_SL 138880
#define FB_TOTAL 140416

template<int K>
__global__ void __launch_bounds__(512, 1) k_fused(const float* __restrict__ X) {
    constexpr int NK16 = (3 * K) / 16;   // 6 or 12
    constexpr int HALF = K / 2;
    constexpr int NQ   = NK16 * 2;       // uint4 per B row
    extern __shared__ char smem[];
    __nv_bfloat16* As = (__nv_bfloat16*)smem;
    float* Qs = (float*)(smem + FB_QS);
    float* hs = (float*)(smem + FB_HS);  // [buf][c01][ECAP]
    int*   sl = (int*)(smem + FB_SL);

    int t = threadIdx.x, w = t >> 5, lane = t & 31;
    int n0 = blockIdx.x * NODE_G;
    int nend = min(n0 + NODE_G, NN);
    int p0 = g_off[n0];
    int p1 = g_off[nend];
    int ce = p1 - p0;
    if (ce <= 0) return;
    int ceM = min(ce, ECAP);
    int EW = (ceM + 15) >> 4;          // edges owned per warp (<= 24)
    int eBase = w * EW;

    u32 a_base = smem_u32(As);
    u32 b_base = smem_u32(smem + FB_BS);
    u32 h_base = smem_u32(hs);

    // ---- prefetch B(0) + hs(0) (one group) ----
    {
        const char* Wsrc = (const char*)g_Wbf;
        for (int i = t; i < 128 * NQ; i += 512) {
            int r = i / NQ, q = i - r * NQ;
            cpasync16(b_base + (u32)(r * 400 + q * 16), Wsrc + (size_t)r * 384 + q * 16);
        }
        for (int i = t; i < 2 * ceM; i += 512) {
            int c01 = (i >= ceM) ? 1 : 0;
            int e = i - c01 * ceM;
            cpasync4(h_base + (u32)((c01 * ECAP + e) * 4),
                     g_Ht + (size_t)c01 * NE + p0 + e);
        }
        cp_commit();
    }

    // ---- A' fill: [hi | hi | lo] ----
    for (int idx = t; idx < MPAD * HALF; idx += 512) {
        int r = idx / HALF, kp = idx - r * HALF;
        int k = kp * 2;
        int n = n0 + r;
        float v0 = 0.f, v1 = 0.f;
        if (r < NODE_G && n < NN) {
            v0 = X[(size_t)n * K + k];
            v1 = X[(size_t)n * K + k + 1];
        }
        __nv_bfloat16 h0 = __float2bfloat16(v0);
        __nv_bfloat16 h1 = __float2bfloat16(v1);
        __nv_bfloat16 l0 = __float2bfloat16(v0 - __bfloat162float(h0));
        __nv_bfloat16 l1 = __float2bfloat16(v1 - __bfloat162float(h1));
        u32 hp = (u32)__bfloat16_as_ushort(h0) | ((u32)__bfloat16_as_ushort(h1) << 16);
        u32 lp = (u32)__bfloat16_as_ushort(l0) | ((u32)__bfloat16_as_ushort(l1) << 16);
        u32* Arow = (u32*)As + r * 100;
        Arow[kp]            = hp;
        Arow[HALF + kp]     = hp;
        Arow[2 * HALF + kp] = lp;
    }
    for (int i = t; i < ceM; i += 512) sl[i] = g_psrc[p0 + i] - n0;

    int wm = (w & 1) * 48;
    int wn = (w >> 1) * 16;

    float2 eacc[EWMAX];
#pragma unroll
    for (int j = 0; j < EWMAX; j++) eacc[j] = make_float2(0.f, 0.f);

    for (int cb = 0; cb < 64; cb++) {
        int buf = cb & 1;
        cp_wait0();
        __syncthreads();   // B(cb)+hs(cb) ready; edge(cb-1) done reading Qs

        // ---- mma: 96x128, warp = 48x16, acc 6 frags ----
        float acc[3][2][4];
#pragma unroll
        for (int mi = 0; mi < 3; mi++)
#pragma unroll
            for (int jb = 0; jb < 2; jb++)
#pragma unroll
                for (int q = 0; q < 4; q++) acc[mi][jb][q] = 0.f;
#pragma unroll
        for (int ks = 0; ks < NK16; ks++) {
            int k0 = ks * 16;
            u32 a[3][4];
#pragma unroll
            for (int mi = 0; mi < 3; mi++) {
                u32 addr = a_base + (u32)(((wm + mi * 16 + (lane & 15)) * ASTRIDE +
                                            k0 + (lane >> 4) * 8) * 2);
                ldsm_x4(a[mi][0], a[mi][1], a[mi][2], a[mi][3], addr);
            }
            u32 b[2][2];
#pragma unroll
            for (int jb = 0; jb < 2; jb++) {
                u32 addr = b_base + (u32)(((wn + jb * 8 + (lane & 7)) * ASTRIDE +
                                            k0 + ((lane >> 3) & 1) * 8) * 2);
                ldsm_x2(b[jb][0], b[jb][1], addr);
            }
#pragma unroll
            for (int mi = 0; mi < 3; mi++)
#pragma unroll
                for (int jb = 0; jb < 2; jb++)
                    mma16816(acc[mi][jb], a[mi], b[jb]);
        }
        __syncthreads();   // all warps done reading Bs

        // ---- prefetch B(cb+1) + hs(cb+1) (lands during Qs-write + edge phase) ----
        if (cb < 63) {
            const char* Wn = (const char*)g_Wbf + (size_t)(cb + 1) * 128 * 384;
            for (int i = t; i < 128 * NQ; i += 512) {
                int r = i / NQ, q = i - r * NQ;
                cpasync16(b_base + (u32)(r * 400 + q * 16), Wn + (size_t)r * 384 + q * 16);
            }
            const float* Hn = g_Ht + (size_t)(2 * (cb + 1)) * NE + p0;
            u32 hdst = h_base + (u32)((buf ^ 1) * 2 * ECAP * 4);
            for (int i = t; i < 2 * ceM; i += 512) {
                int c01 = (i >= ceM) ? 1 : 0;
                int e = i - c01 * ceM;
                cpasync4(hdst + (u32)((c01 * ECAP + e) * 4), Hn + (size_t)c01 * NE + e);
            }
        }
        cp_commit();

        // ---- write Qs ----
#pragma unroll
        for (int mi = 0; mi < 3; mi++) {
            int m0 = wm + mi * 16 + (lane >> 2);
#pragma unroll
            for (int jb = 0; jb < 2; jb++) {
                int col = wn + jb * 8 + (lane & 3) * 2;
                if (m0 < NODE_G)
                    *(float2*)&Qs[m0 * QSTRIDE + col] = make_float2(acc[mi][jb][0], acc[mi][jb][1]);
                if (m0 + 8 < NODE_G)
                    *(float2*)&Qs[(m0 + 8) * QSTRIDE + col] = make_float2(acc[mi][jb][2], acc[mi][jb][3]);
            }
        }
        __syncthreads();   // Qs visible

        // ---- edge phase: register accumulation, warp-owned edges ----
        {
            const float* hb0 = hs + buf * 2 * ECAP;
            const float* hb1 = hb0 + ECAP;
#pragma unroll
            for (int j = 0; j < EWMAX; j++) {
                int e = eBase + j;
                if (j < EW && e < ceM) {
                    int s = sl[e];
                    float h0 = hb0[e];
                    float h1 = hb1[e];
                    float2 q0 = *(const float2*)&Qs[s * QSTRIDE + 2 * lane];
                    float2 q1 = *(const float2*)&Qs[s * QSTRIDE + 64 + 2 * lane];
                    eacc[j].x += h0 * q0.x + h1 * q1.x;
                    eacc[j].y += h0 * q0.y + h1 * q1.y;
                }
            }
        }
        // ---- overflow edges (rare): direct atomic per cb ----
        for (int e = ceM + w; e < ce; e += 16) {
            int p = p0 + e;
            float h0 = g_Ht[(size_t)(2 * cb) * NE + p];
            float h1 = g_Ht[(size_t)(2 * cb + 1) * NE + p];
            int sg = g_psrc[p];
            int s = sg - n0;
            int d = g_pdst[p];
            float2 q0 = *(const float2*)&Qs[s * QSTRIDE + 2 * lane];
            float2 q1 = *(const float2*)&Qs[s * QSTRIDE + 64 + 2 * lane];
            float ax = h0 * q0.x + h1 * q1.x;
            float ay = h0 * q0.y + h1 * q1.y;
            if (cb == 0) {
                ax += g_xb[(size_t)sg * 64 + 2 * lane];
                ay += g_xb[(size_t)sg * 64 + 2 * lane + 1];
            }
            atomicAdd(&g_agg[(size_t)d * 64 + 2 * lane], ax);
            atomicAdd(&g_agg[(size_t)d * 64 + 2 * lane + 1], ay);
        }
    }

    // ---- flush register accumulators: agg[dst] += eacc + xb[src] ----
#pragma unroll
    for (int j = 0; j < EWMAX; j++) {
        int e = eBase + j;
        if (j < EW && e < ceM) {
            int p = p0 + e;
            int d = g_pdst[p];
            int sg = n0 + sl[e];
            float2 xv = *(const float2*)&g_xb[(size_t)sg * 64 + 2 * lane];
            atomicAdd(&g_agg[(size_t)d * 64 + 2 * lane],     eacc[j].x + xv.x);
            atomicAdd(&g_agg[(size_t)d * 64 + 2 * lane + 1], eacc[j].y + xv.y);
        }
    }
}

// ---------------- batch norm ----------------
__global__ void k_bn_zero() {
    int t = threadIdx.x;
    if (t < HID) { g_bnsum[t] = 0.f; g_bnsq[t] = 0.f; }
}
__global__ void k_bn_stats() {
    int t = threadIdx.x;
    int o = t & 63, s = t >> 6;
    float sum = 0.f, sq = 0.f;
    for (int n = blockIdx.x * 4 + s; n < NN; n += gridDim.x * 4) {
        float v = g_agg[(size_t)n * 64 + o];
        sum += v; sq += v * v;
    }
    __shared__ float ssum[256], ssq[256];
    ssum[t] = sum; ssq[t] = sq;
    __syncthreads();
    if (t < 128) { ssum[t] += ssum[t + 128]; ssq[t] += ssq[t + 128]; }
    __syncthreads();
    if (t < 64) {
        atomicAdd(&g_bnsum[t], ssum[t] + ssum[t + 64]);
        atomicAdd(&g_bnsq [t], ssq [t] + ssq [t + 64]);
    }
}
__global__ void k_bn_apply(const float* __restrict__ gamma,
                           const float* __restrict__ beta,
                           float* __restrict__ xout) {
    int i = blockIdx.x * blockDim.x + threadIdx.x;
    if (i >= NN * 64) return;
    int o = i & 63;
    float mu  = g_bnsum[o] * (1.f / NN);
    float var = g_bnsq[o] * (1.f / NN) - mu * mu;
    float v = gamma[o] * (g_agg[i] - mu) * rsqrtf(var + EPS_BN) + beta[o];
    xout[i] = fmaxf(v, 0.f);
}

// ---------------- pooling + final MLP ----------------
__global__ void k_pool_init() {
    int i = blockIdx.x * blockDim.x + threadIdx.x;
    if (i < NG * HID) g_pool[i] = 0.f;
}
__global__ void k_pool(const float* __restrict__ xl, const int* __restrict__ batch) {
    int i = blockIdx.x * blockDim.x + threadIdx.x;
    if (i >= NN * 64) return;
    int n = i >> 6, o = i & 63;
    int g = batch[n];
    atomicMax(reinterpret_cast<unsigned int*>(&g_pool[g * 64 + o]), __float_as_uint(xl[i]));
}
__global__ void k_final(const float* __restrict__ u,
                        const float* __restrict__ w1, const float* __restrict__ b1,
                        const float* __restrict__ w2, const float* __restrict__ b2,
                        float* __restrict__ out) {
    int g = blockIdx.x;
    int j = threadIdx.x;
    __shared__ float cat[72];
    __shared__ float red[64];
    if (j < 64) cat[j] = g_pool[g * 64 + j];
    if (j < 8)  cat[64 + j] = u[g * 8 + j];
    __syncthreads();
    float h = b1[j];
#pragma unroll
    for (int k = 0; k < 72; k++) h += cat[k] * w1[k * 64 + j];
    h = fmaxf(h, 0.f);
    red[j] = h * w2[j];
    __syncthreads();
    for (int s = 32; s > 0; s >>= 1) {
        if (j < s) red[j] += red[j + s];
        __syncthreads();
    }
    if (j == 0) out[g] = red[0] + b2[0];
}

// ---------------- host ----------------
extern "C" void kernel_launch(void* const* d_in, const int* in_sizes, int n_in,
                              void* d_out, int out_size) {
    const float* x       = (const float*)d_in[0];
    const int*   ei      = (const int*)  d_in[1];
    const float* ea      = (const float*)d_in[2];
    const int*   batch   = (const int*)  d_in[3];
    const float* u       = (const float*)d_in[4];
    const float* enn0_w1 = (const float*)d_in[5];
    const float* enn0_b1 = (const float*)d_in[6];
    const float* enn0_w2 = (const float*)d_in[7];
    const float* enn0_b2 = (const float*)d_in[8];
    const float* root0   = (const float*)d_in[9];
    const float* bias0   = (const float*)d_in[10];
    const float* gamma0  = (const float*)d_in[11];
    const float* beta0   = (const float*)d_in[12];
    const float* enn_w1  = (const float*)d_in[13];
    const float* enn_b1  = (const float*)d_in[14];
    const float* enn_w2  = (const float*)d_in[15];
    const float* enn_b2  = (const float*)d_in[16];
    const float* root_l  = (const float*)d_in[17];
    const float* bias_l  = (const float*)d_in[18];
    const float* gamma_l = (const float*)d_in[19];
    const float* beta_l  = (const float*)d_in[20];
    const float* pp_w1   = (const float*)d_in[21];
    const float* pp_b1   = (const float*)d_in[22];
    const float* pp_w2   = (const float*)d_in[23];
    const float* pp_b2   = (const float*)d_in[24];

    const int* src  = ei;
    const int* dste = ei + NE;

    cudaFuncSetAttribute(k_fused<IN_CH>, cudaFuncAttributeMaxDynamicSharedMemorySize, FB_TOTAL);
    cudaFuncSetAttribute(k_fused<HID>,  cudaFuncAttributeMaxDynamicSharedMemorySize, FB_TOTAL);

    void* pA; cudaGetSymbolAddress(&pA, g_xA);
    void* pB; cudaGetSymbolAddress(&pB, g_xB);
    float* xA = (float*)pA;
    float* xB = (float*)pB;

    k_zero_cnt<<<(NN + 255) / 256, 256>>>();
    k_count  <<<(NE + 255) / 256, 256>>>(src);
    k_scan   <<<1, 1024>>>();
    k_scatter<<<(NE + 255) / 256, 256>>>(src, dste);

    const float* xin = x;
    float* xout = xA;

    for (int l = 0; l < 4; l++) {
        const float *w1, *b1, *w2, *b2, *rt, *bs, *gm, *bt;
        int C = (l == 0) ? IN_CH : HID;
        if (l == 0) {
            w1 = enn0_w1; b1 = enn0_b1; w2 = enn0_w2; b2 = enn0_b2;
            rt = root0; bs = bias0; gm = gamma0; bt = beta0;
        } else {
            int m = l - 1;
            w1 = enn_w1 + (size_t)m * EIN * 128;
            b1 = enn_b1 + (size_t)m * 128;
            w2 = enn_w2 + (size_t)m * 128 * 4096;
            b2 = enn_b2 + (size_t)m * 4096;
            rt = root_l + (size_t)m * 64 * 64;
            bs = bias_l + (size_t)m * 64;
            gm = gamma_l + (size_t)m * 64;
            bt = beta_l + (size_t)m * 64;
        }
        k_wsplit2 <<<128, 256>>>(w2, C);
        k_edge_h  <<<(NE + EPB - 1) / EPB, 128>>>(ea, w1, b1);
        k_node_pre<<<(NN + 3) / 4, 256>>>(xin, C, rt, bs, b2);
        if (l == 0) k_fused<IN_CH><<<148, 512, FB_TOTAL>>>(xin);
        else        k_fused<HID> <<<148, 512, FB_TOTAL>>>(xin);
        k_bn_zero <<<1, 64>>>();
        k_bn_stats<<<128, 256>>>();
        k_bn_apply<<<(NN * 64 + 255) / 256, 256>>>(gm, bt, xout);

        xin = xout;
        xout = (xout == xA) ? xB : xA;
    }

    k_pool_init<<<(NG * HID + 255) / 256, 256>>>();
    k_pool     <<<(NN * 64 + 255) / 256, 256>>>(xin, batch);
    k_final    <<<NG, 64>>>(u, pp_w1, pp_b1, pp_w2, pp_b2, (float*)d_out);
}